// round 1
// baseline (speedup 1.0000x reference)
#include <cuda_runtime.h>
#include <cstdint>

// RoiPooling: crop_and_resize of img[0] (28x28x512 f32, NHWC) at 2048 fixed-size
// boxes (window 4/28 normalized) into 7x7 bilinear crops.
// Output (flat) = crops[n, py, px, c], n in [0,2048), 51,380,224 f32.
//
// Strategy: 1 CTA per ROI. Each ROI's 7x7 sample grid spans ~3.9 px, so the
// CTA's image working set (~60-70 KB) stays L1-resident across all 49 samples.
// 512 threads = 128 float4 channel-groups x 4 sample slots.

#define RP_H 28
#define RP_W 28
#define RP_C 512
#define RP_POOL 7
#define RP_NROI 2048

__global__ __launch_bounds__(512, 4)
void roi_pool_kernel(const float* __restrict__ img,
                     const float* __restrict__ rois,
                     float4* __restrict__ out)
{
    const int n   = blockIdx.x;          // roi index 0..2047
    const int tid = threadIdx.x;
    const int c4  = tid & 127;           // float4 channel group (c = 4*c4)
    const int s0  = tid >> 7;            // sample slot 0..3

    // rois flat: roi n -> [.,.,., x1, y1] at offset 5n
    const float x1 = __ldg(&rois[n * 5 + 3]);
    const float y1 = __ldg(&rois[n * 5 + 4]);

    // Replicate reference arithmetic exactly (f32, same association order):
    //   x2 = x1 + float(4/28);  step = ((x2-x1)*27)/6;  xs = x1*27 + px*step
    const float win = (float)(4.0 / 28.0);
    const float x2 = __fadd_rn(x1, win);
    const float y2 = __fadd_rn(y1, win);
    const float stepx = __fdiv_rn(__fmul_rn(__fsub_rn(x2, x1), 27.0f), 6.0f);
    const float stepy = __fdiv_rn(__fmul_rn(__fsub_rn(y2, y1), 27.0f), 6.0f);
    const float bx = __fmul_rn(x1, 27.0f);
    const float by = __fmul_rn(y1, 27.0f);

    const float4* __restrict__ im = (const float4*)img;   // [(y*28+x)*128 + c4]
    float4* __restrict__ o = out + (size_t)n * (RP_POOL * RP_POOL * (RP_C / 4));

    #pragma unroll
    for (int s = s0; s < RP_POOL * RP_POOL; s += 4) {
        const int py = s / RP_POOL;
        const int px = s % RP_POOL;

        const float ys = __fadd_rn(by, __fmul_rn((float)py, stepy));
        const float xs = __fadd_rn(bx, __fmul_rn((float)px, stepx));

        const float y0f = floorf(ys);
        const float x0f = floorf(xs);
        const float ly = ys - y0f;
        const float lx = xs - x0f;
        const float oly = 1.0f - ly;

        int yi0 = (int)y0f;
        int xi0 = (int)x0f;
        int yi1 = yi0 + 1;
        int xi1 = xi0 + 1;
        yi0 = min(max(yi0, 0), RP_H - 1);
        yi1 = min(max(yi1, 0), RP_H - 1);
        xi0 = min(max(xi0, 0), RP_W - 1);
        xi1 = min(max(xi1, 0), RP_W - 1);

        const float m = (ys >= 0.0f && ys <= (float)(RP_H - 1) &&
                         xs >= 0.0f && xs <= (float)(RP_W - 1)) ? 1.0f : 0.0f;

        const float4 tl = im[(yi0 * RP_W + xi0) * 128 + c4];
        const float4 tr = im[(yi0 * RP_W + xi1) * 128 + c4];
        const float4 bl = im[(yi1 * RP_W + xi0) * 128 + c4];
        const float4 br = im[(yi1 * RP_W + xi1) * 128 + c4];

        float4 r;
        r.x = ((tl.x + (tr.x - tl.x) * lx) * oly + (bl.x + (br.x - bl.x) * lx) * ly) * m;
        r.y = ((tl.y + (tr.y - tl.y) * lx) * oly + (bl.y + (br.y - bl.y) * lx) * ly) * m;
        r.z = ((tl.z + (tr.z - tl.z) * lx) * oly + (bl.z + (br.z - bl.z) * lx) * ly) * m;
        r.w = ((tl.w + (tr.w - tl.w) * lx) * oly + (bl.w + (br.w - bl.w) * lx) * ly) * m;

        o[s * 128 + c4] = r;
    }
}

extern "C" void kernel_launch(void* const* d_in, const int* in_sizes, int n_in,
                              void* d_out, int out_size)
{
    const float* img  = (const float*)d_in[0];   // (16,28,28,512) f32; only img[0] used
    const float* rois = (const float*)d_in[1];   // (16,640) f32
    float4* out = (float4*)d_out;                // 51,380,224 f32

    roi_pool_kernel<<<RP_NROI, 512>>>(img, rois, out);
}

// round 2
// speedup vs baseline: 1.1043x; 1.1043x over previous
#include <cuda_runtime.h>
#include <cstdint>

// RoiPooling: crop_and_resize of img[0] (28x28x512 f32, NHWC) at 2048 boxes
// (fixed window 4/28) into 7x7 bilinear crops. Output 2048*7*7*512 f32.
//
// R2 strategy: 1 CTA = 1 ROI, 128 threads = 128 float4 channel groups.
// Separable bilinear: x-interp each image row once into registers, rolling
// 2-row window reuse across output rows (stepy < 1 so floor(ys) steps by 0/1).

#define RP_H 28
#define RP_W 28
#define RP_POOL 7
#define RP_NROI 2048

__device__ __forceinline__ float4 lerp4(float4 a, float4 b, float t) {
    float4 r;
    r.x = a.x + (b.x - a.x) * t;
    r.y = a.y + (b.y - a.y) * t;
    r.z = a.z + (b.z - a.z) * t;
    r.w = a.w + (b.w - a.w) * t;
    return r;
}

__global__ __launch_bounds__(128)
void roi_pool_kernel(const float* __restrict__ img,
                     const float* __restrict__ rois,
                     float4* __restrict__ out)
{
    const int n  = blockIdx.x;           // roi 0..2047
    const int c4 = threadIdx.x;          // float4 channel group 0..127

    // rois flat: roi n -> [.,.,., x1, y1] at offset 5n
    const float x1 = __ldg(&rois[n * 5 + 3]);
    const float y1 = __ldg(&rois[n * 5 + 4]);

    // Replicate reference f32 arithmetic exactly:
    //   x2 = x1 + float(4/28); step = ((x2-x1)*27)/6; xs = x1*27 + px*step
    const float win = (float)(4.0 / 28.0);
    const float x2 = __fadd_rn(x1, win);
    const float y2 = __fadd_rn(y1, win);
    const float stepx = __fdiv_rn(__fmul_rn(__fsub_rn(x2, x1), 27.0f), 6.0f);
    const float stepy = __fdiv_rn(__fmul_rn(__fsub_rn(y2, y1), 27.0f), 6.0f);
    const float bx = __fmul_rn(x1, 27.0f);
    const float by = __fmul_rn(y1, 27.0f);

    // Per-px x data (warp-uniform; unrolled so register indexing is static)
    float lx[RP_POOL], mx[RP_POOL];
    int xo0[RP_POOL], xo1[RP_POOL];     // float4 offsets within a row
    #pragma unroll
    for (int px = 0; px < RP_POOL; px++) {
        const float xs = __fadd_rn(bx, __fmul_rn((float)px, stepx));
        const float x0f = floorf(xs);
        lx[px] = xs - x0f;
        mx[px] = (xs <= (float)(RP_W - 1)) ? 1.0f : 0.0f;  // xs >= 0 always
        int xi0 = (int)x0f;
        int xi1 = xi0 + 1;
        xi0 = min(max(xi0, 0), RP_W - 1);
        xi1 = min(max(xi1, 0), RP_W - 1);
        xo0[px] = xi0 * 128;
        xo1[px] = xi1 * 128;
    }

    const float4* __restrict__ im = (const float4*)img;  // [(y*28+x)*128 + c4]
    float4* __restrict__ o = out + (size_t)n * (RP_POOL * RP_POOL * 128) + c4;

    float4 top[RP_POOL], bot[RP_POOL];   // x-interpolated rows clamp(y0), clamp(y0+1)
    int prevY0 = -12345;

    #pragma unroll
    for (int py = 0; py < RP_POOL; py++) {
        const float ys = __fadd_rn(by, __fmul_rn((float)py, stepy));

        if (ys > (float)(RP_H - 1)) {
            // masked row (ys monotonically increasing; exact zeros)
            const float4 z = make_float4(0.f, 0.f, 0.f, 0.f);
            #pragma unroll
            for (int px = 0; px < RP_POOL; px++)
                o[(py * RP_POOL + px) * 128] = z;
            continue;
        }

        const float y0f = floorf(ys);
        const float ly = ys - y0f;
        const int y0 = (int)y0f;                       // >= 0 (by >= 0)
        const int y0c = min(y0, RP_H - 1);
        const int y1c = min(y0 + 1, RP_H - 1);

        if (py == 0) {
            const float4* __restrict__ r0 = im + y0c * (RP_W * 128) + c4;
            const float4* __restrict__ r1 = im + y1c * (RP_W * 128) + c4;
            #pragma unroll
            for (int px = 0; px < RP_POOL; px++) {
                top[px] = lerp4(r0[xo0[px]], r0[xo1[px]], lx[px]);
                bot[px] = lerp4(r1[xo0[px]], r1[xo1[px]], lx[px]);
            }
        } else if (y0 != prevY0) {
            // stepy in (0,1): y0 advanced by exactly 1 -> bot becomes top
            #pragma unroll
            for (int px = 0; px < RP_POOL; px++) top[px] = bot[px];
            const float4* __restrict__ r1 = im + y1c * (RP_W * 128) + c4;
            #pragma unroll
            for (int px = 0; px < RP_POOL; px++)
                bot[px] = lerp4(r1[xo0[px]], r1[xo1[px]], lx[px]);
        }
        prevY0 = y0;

        const float oly = 1.0f - ly;
        #pragma unroll
        for (int px = 0; px < RP_POOL; px++) {
            const float m = mx[px];
            float4 r;
            r.x = (top[px].x * oly + bot[px].x * ly) * m;
            r.y = (top[px].y * oly + bot[px].y * ly) * m;
            r.z = (top[px].z * oly + bot[px].z * ly) * m;
            r.w = (top[px].w * oly + bot[px].w * ly) * m;
            o[(py * RP_POOL + px) * 128] = r;
        }
    }
}

extern "C" void kernel_launch(void* const* d_in, const int* in_sizes, int n_in,
                              void* d_out, int out_size)
{
    const float* img  = (const float*)d_in[0];   // (16,28,28,512) f32; only img[0] used
    const float* rois = (const float*)d_in[1];   // (16,640) f32
    float4* out = (float4*)d_out;                // 51,380,224 f32

    roi_pool_kernel<<<RP_NROI, 128>>>(img, rois, out);
}